// round 10
// baseline (speedup 1.0000x reference)
#include <cuda_runtime.h>
#include <cuda_bf16.h>
#include <math.h>
#include <stdint.h>

#define V 50280
#define DM 768
#define NLY 4
#define DS 16
#define DC 4
#define DTR 48
#define ROH 512
#define DI 1536
#define BB 2
#define LL 128
#define BL 256                       // BB*LL
#define DIDS (DI*DS)                 // 24576
#define HID_LAYER_STRIDE (BL*DIDS)   // 6291456

// ---------------- scratch (device globals; no allocation allowed) ----------
__device__ float g_x[BL * DM];
__device__ float g_xn[BL * DM];
__device__ float g_xz[BL * 2 * DI];
__device__ float g_xconv[BL * DI];
__device__ float g_dbc[BL * 80];
__device__ float g_delta[BL * DI];
__device__ float g_y[BL * DI];
__device__ float g_h1[BL * ROH];
__device__ float g_h2[BL * 256];

// ---------------- embedding gather ----------------
__global__ void k_embed(const int* __restrict__ ids, const float* __restrict__ embed) {
    int i = blockIdx.x * blockDim.x + threadIdx.x;
    if (i < BL * DM) {
        int r = i / DM, c = i % DM;
        g_x[i] = embed[(size_t)ids[r] * DM + c];
    }
}

// ---------------- rmsnorm (one block per row) ----------------
__global__ void k_rmsnorm(const float* __restrict__ x, const float* __restrict__ w,
                          float* __restrict__ out) {
    int r = blockIdx.x;
    int tid = threadIdx.x;
    __shared__ float red[256];
    float s = 0.f;
    for (int c = tid; c < DM; c += 256) {
        float v = x[r * DM + c];
        s += v * v;
    }
    red[tid] = s;
    __syncthreads();
    for (int o = 128; o > 0; o >>= 1) {
        if (tid < o) red[tid] += red[tid + o];
        __syncthreads();
    }
    float scale = rsqrtf(red[0] / DM + 1e-5f);
    for (int c = tid; c < DM; c += 256) out[r * DM + c] = x[r * DM + c] * scale * w[c];
}

// ---------------- scalar fp32 GEMM (ro2 only) ----------------
template <int ACT>
__global__ void k_gemm(const float* __restrict__ A, const float* __restrict__ B,
                       float* __restrict__ C, const float* __restrict__ bias,
                       int N, int lda, int ldb, int ldc, int kcount) {
    __shared__ float As[16][68];
    __shared__ float Bs[16][68];
    int tid = threadIdx.x;
    int bm = blockIdx.y * 64, bn = blockIdx.x * 64;

    float acc[4][4] = {};
    int a_r = tid >> 2, a_k = (tid & 3) * 4;
    int ty = tid >> 4, tx = tid & 15;

    for (int k0 = 0; k0 < kcount; k0 += 16) {
        float4 av = *(const float4*)(A + (size_t)(bm + a_r) * lda + k0 + a_k);
        As[a_k + 0][a_r] = av.x;
        As[a_k + 1][a_r] = av.y;
        As[a_k + 2][a_r] = av.z;
        As[a_k + 3][a_r] = av.w;
        int b_r = tid >> 4, b_c = (tid & 15) * 4;
        float4 bv = *(const float4*)(B + (size_t)(k0 + b_r) * ldb + bn + b_c);
        *(float4*)&Bs[b_r][b_c] = bv;
        __syncthreads();
#pragma unroll
        for (int kk = 0; kk < 16; kk++) {
            float4 a = *(const float4*)&As[kk][ty * 4];
            float4 b = *(const float4*)&Bs[kk][tx * 4];
            float ar[4] = {a.x, a.y, a.z, a.w};
            float br[4] = {b.x, b.y, b.z, b.w};
#pragma unroll
            for (int i = 0; i < 4; i++)
#pragma unroll
                for (int j = 0; j < 4; j++) acc[i][j] = fmaf(ar[i], br[j], acc[i][j]);
        }
        __syncthreads();
    }
#pragma unroll
    for (int i = 0; i < 4; i++) {
        int m = bm + ty * 4 + i;
#pragma unroll
        for (int j = 0; j < 4; j++) {
            int n = bn + tx * 4 + j;
            float v = acc[i][j] + bias[n];
            if (ACT == 1) v = fmaxf(v, 0.f);
            C[(size_t)m * ldc + n] = v;
        }
    }
}

// ---------------- tensor-core GEMM: split-bf16 (3 mma), 128x64, BK=64 ------
__device__ __forceinline__ uint32_t smem_u32(const void* p) {
    uint32_t a;
    asm("{ .reg .u64 t; cvta.to.shared.u64 t, %1; cvt.u32.u64 %0, t; }" : "=r"(a) : "l"(p));
    return a;
}
__device__ __forceinline__ void mma_bf16(float* c, const uint32_t* a, const uint32_t* b) {
    asm volatile(
        "mma.sync.aligned.m16n8k16.row.col.f32.bf16.bf16.f32 "
        "{%0,%1,%2,%3}, {%4,%5,%6,%7}, {%8,%9}, {%0,%1,%2,%3};\n"
        : "+f"(c[0]), "+f"(c[1]), "+f"(c[2]), "+f"(c[3])
        : "r"(a[0]), "r"(a[1]), "r"(a[2]), "r"(a[3]), "r"(b[0]), "r"(b[1]));
}
__device__ __forceinline__ void ldsm4(uint32_t* r, uint32_t addr) {
    asm volatile("ldmatrix.sync.aligned.m8n8.x4.shared.b16 {%0,%1,%2,%3}, [%4];"
                 : "=r"(r[0]), "=r"(r[1]), "=r"(r[2]), "=r"(r[3]) : "r"(addr));
}

#define PAD 72
#define SM_MMA ((128 * PAD * 2 + 64 * PAD * 2) * 2)   // 55296 bytes

template <bool BT, bool FEAT, int MODE, bool NGUARD, bool HASBIAS>
__global__ void __launch_bounds__(256, 2)
k_mma(const float* __restrict__ A, const float* __restrict__ B, float* __restrict__ C,
      const float* __restrict__ bias, int N, int lda, int ldb, int ldc, int kcount) {
    extern __shared__ __nv_bfloat16 smem[];
    __nv_bfloat16 (*Ah)[PAD] = (__nv_bfloat16(*)[PAD])(smem);
    __nv_bfloat16 (*Al)[PAD] = (__nv_bfloat16(*)[PAD])(smem + 128 * PAD);
    __nv_bfloat16 (*Bh)[PAD] = (__nv_bfloat16(*)[PAD])(smem + 2 * 128 * PAD);
    __nv_bfloat16 (*Bl)[PAD] = (__nv_bfloat16(*)[PAD])(smem + 2 * 128 * PAD + 64 * PAD);

    int tid = threadIdx.x;
    int lane = tid & 31, warp = tid >> 5;
    int wm = warp & 3, wn = warp >> 2;
    int bm = blockIdx.y * 128, bn = blockIdx.x * 64;
    int kbeg = blockIdx.z * kcount;
    int qrow = lane >> 2, qcol = (lane & 3) * 2;

    const float* Ap;
    int alda = lda;
    if (FEAT) {
        int layer = kbeg / DIDS;
        Ap = A + (size_t)layer * HID_LAYER_STRIDE + (kbeg % DIDS);
        alda = DIDS;
    } else {
        Ap = A + kbeg;
    }
    const float* Bp = BT ? (B + kbeg) : (B + (size_t)kbeg * ldb);

    float acc[2][4][4] = {};

    const int a_row = (lane & 15);
    const int a_koff = ((lane >> 4) & 1) * 8;
    const int b_rowsel = (lane & 7) + ((lane >> 4) & 1) * 8;
    const int b_koff = ((lane >> 3) & 1) * 8;

    for (int k0 = 0; k0 < kcount; k0 += 64) {
        // ---- stage A: 128x64 fp32 -> hi/lo bf16 ----
#pragma unroll
        for (int i = 0; i < 8; i++) {
            int id = tid + i * 256;
            int r = id >> 4, kq = (id & 15) * 4;
            float4 v = *(const float4*)(Ap + (size_t)(bm + r) * alda + k0 + kq);
            __nv_bfloat16 h0 = __float2bfloat16(v.x), h1 = __float2bfloat16(v.y);
            __nv_bfloat16 h2 = __float2bfloat16(v.z), h3 = __float2bfloat16(v.w);
            *(__nv_bfloat162*)&Ah[r][kq] = __halves2bfloat162(h0, h1);
            *(__nv_bfloat162*)&Ah[r][kq + 2] = __halves2bfloat162(h2, h3);
            *(__nv_bfloat162*)&Al[r][kq] = __halves2bfloat162(
                __float2bfloat16(v.x - __bfloat162float(h0)),
                __float2bfloat16(v.y - __bfloat162float(h1)));
            *(__nv_bfloat162*)&Al[r][kq + 2] = __halves2bfloat162(
                __float2bfloat16(v.z - __bfloat162float(h2)),
                __float2bfloat16(v.w - __bfloat162float(h3)));
        }
        // ---- stage B: 64x64 ----
        if (BT) {
#pragma unroll
            for (int i = 0; i < 4; i++) {
                int id = tid + i * 256;
                int nr = id >> 4, kq = (id & 15) * 4;
                float4 v = make_float4(0.f, 0.f, 0.f, 0.f);
                if (!NGUARD || (bn + nr) < N)
                    v = *(const float4*)(Bp + (size_t)(bn + nr) * ldb + k0 + kq);
                __nv_bfloat16 h0 = __float2bfloat16(v.x), h1 = __float2bfloat16(v.y);
                __nv_bfloat16 h2 = __float2bfloat16(v.z), h3 = __float2bfloat16(v.w);
                *(__nv_bfloat162*)&Bh[nr][kq] = __halves2bfloat162(h0, h1);
                *(__nv_bfloat162*)&Bh[nr][kq + 2] = __halves2bfloat162(h2, h3);
                *(__nv_bfloat162*)&Bl[nr][kq] = __halves2bfloat162(
                    __float2bfloat16(v.x - __bfloat162float(h0)),
                    __float2bfloat16(v.y - __bfloat162float(h1)));
                *(__nv_bfloat162*)&Bl[nr][kq + 2] = __halves2bfloat162(
                    __float2bfloat16(v.z - __bfloat162float(h2)),
                    __float2bfloat16(v.w - __bfloat162float(h3)));
            }
        } else {
#pragma unroll
            for (int i = 0; i < 4; i++) {
                int id = tid + i * 256;
                int kr = id >> 4, nq = (id & 15) * 4;
                float fv[4];
                if (!NGUARD || (bn + nq + 3) < N) {
                    float4 v = *(const float4*)(Bp + (size_t)(k0 + kr) * ldb + bn + nq);
                    fv[0] = v.x; fv[1] = v.y; fv[2] = v.z; fv[3] = v.w;
                } else {
#pragma unroll
                    for (int j = 0; j < 4; j++)
                        fv[j] = (bn + nq + j) < N ? Bp[(size_t)(k0 + kr) * ldb + bn + nq + j] : 0.f;
                }
#pragma unroll
                for (int j = 0; j < 4; j++) {
                    __nv_bfloat16 h = __float2bfloat16(fv[j]);
                    Bh[nq + j][kr] = h;
                    Bl[nq + j][kr] = __float2bfloat16(fv[j] - __bfloat162float(h));
                }
            }
        }
        __syncthreads();
        // ---- compute: 4 k16 steps via ldmatrix ----
#pragma unroll
        for (int ks = 0; ks < 64; ks += 16) {
            uint32_t ah[2][4], al[2][4], bh[2][4], bl[2][4];
#pragma unroll
            for (int mt = 0; mt < 2; mt++) {
                int r0 = wm * 32 + mt * 16 + a_row;
                ldsm4(ah[mt], smem_u32(&Ah[r0][ks + a_koff]));
                ldsm4(al[mt], smem_u32(&Al[r0][ks + a_koff]));
            }
#pragma unroll
            for (int np = 0; np < 2; np++) {
                int n0 = wn * 32 + np * 16 + b_rowsel;
                ldsm4(bh[np], smem_u32(&Bh[n0][ks + b_koff]));
                ldsm4(bl[np], smem_u32(&Bl[n0][ks + b_koff]));
            }
#pragma unroll
            for (int mt = 0; mt < 2; mt++)
#pragma unroll
                for (int np = 0; np < 2; np++)
#pragma unroll
                    for (int j = 0; j < 2; j++) {
                        float* c = acc[mt][np * 2 + j];
                        mma_bf16(c, ah[mt], bh[np] + j * 2);
                        mma_bf16(c, al[mt], bh[np] + j * 2);
                        mma_bf16(c, ah[mt], bl[np] + j * 2);
                    }
        }
        __syncthreads();
    }

    // ---- epilogue ----
#pragma unroll
    for (int mt = 0; mt < 2; mt++)
#pragma unroll
        for (int i = 0; i < 2; i++) {
            int m = bm + wm * 32 + mt * 16 + qrow + i * 8;
#pragma unroll
            for (int nt = 0; nt < 4; nt++)
#pragma unroll
                for (int j = 0; j < 2; j++) {
                    int n = bn + wn * 32 + nt * 8 + qcol + j;
                    if (NGUARD && n >= N) continue;
                    float v = acc[mt][nt][i * 2 + j];
                    if (HASBIAS) v += bias[n];
                    size_t idx = (size_t)m * ldc + n;
                    if (MODE == 0) C[idx] = v;
                    else if (MODE == 1) C[idx] += v;
                    else atomicAdd(&C[idx], v);
                }
        }
}

// ---------------- fused conv+silu, x_proj, dt+softplus (one block per row) --
__global__ void k_cxd(const float* __restrict__ cw, const float* __restrict__ cb,
                      const float* __restrict__ xp, const float* __restrict__ dtw,
                      const float* __restrict__ dtb) {
    int r = blockIdx.x;          // 0..255
    int b = r / LL, t = r % LL;
    int tid = threadIdx.x;       // 256
    __shared__ float sxc[DI];
    __shared__ float part[3][80];
    __shared__ float sdbc[80];

    // causal depthwise conv (DC=4) + silu
    for (int d = tid; d < DI; d += 256) {
        float acc = cb[d];
#pragma unroll
        for (int k = 0; k < DC; k++) {
            int tt = t + k - (DC - 1);
            if (tt >= 0)
                acc = fmaf(cw[d * DC + k], g_xz[(size_t)(b * LL + tt) * (2 * DI) + d], acc);
        }
        acc = acc / (1.f + __expf(-acc));
        sxc[d] = acc;
        g_xconv[r * DI + d] = acc;
    }
    __syncthreads();

    // x_proj: dbc[80] = sxc @ xp (1536x80)
    if (tid < 240) {
        int n = tid % 80, ks = tid / 80;
        float acc = 0.f;
        int k0 = ks * 512;
#pragma unroll 8
        for (int k = 0; k < 512; k++) acc = fmaf(sxc[k0 + k], xp[(size_t)(k0 + k) * 80 + n], acc);
        part[ks][n] = acc;
    }
    __syncthreads();
    if (tid < 80) {
        float v = part[0][tid] + part[1][tid] + part[2][tid];
        sdbc[tid] = v;
        g_dbc[r * 80 + tid] = v;
    }
    __syncthreads();

    // dt: delta[d] = softplus(sdbc[0:48] @ dtw[:,d] + dtb[d])
    for (int d = tid; d < DI; d += 256) {
        float a = dtb[d];
#pragma unroll
        for (int k = 0; k < DTR; k++) a = fmaf(sdbc[k], dtw[(size_t)k * DI + d], a);
        g_delta[r * DI + d] = (a > 20.f) ? a : log1pf(__expf(a));
    }
}

// ---------------- selective scan + fused gate (thread per (b,d,n)) ----------
__global__ void k_scan(const float* __restrict__ A_log_l, float* __restrict__ hidden,
                       const float* __restrict__ Dp, int layer) {
    int tid = blockIdx.x * blockDim.x + threadIdx.x;  // BB*DI*DS = 49152
    int n = tid & 15;
    int d = (tid >> 4) % DI;
    int b = tid / (DI * DS);
    float Adn = -__expf(A_log_l[d * DS + n]);
    float Dd = Dp[d];
    float h = 0.f;
    float* hbase = hidden + (size_t)layer * HID_LAYER_STRIDE;
    for (int t = 0; t < LL; t++) {
        int row = b * LL + t;
        float del = g_delta[row * DI + d];
        float u = g_xconv[row * DI + d];
        float Bn = g_dbc[row * 80 + DTR + n];
        float Cn = g_dbc[row * 80 + DTR + DS + n];
        float dA = __expf(del * Adn);
        h = fmaf(dA, h, del * Bn * u);
        hbase[(size_t)row * DIDS + d * DS + n] = h;
        float p = h * Cn;
        p += __shfl_xor_sync(0xffffffffu, p, 8, 16);
        p += __shfl_xor_sync(0xffffffffu, p, 4, 16);
        p += __shfl_xor_sync(0xffffffffu, p, 2, 16);
        p += __shfl_xor_sync(0xffffffffu, p, 1, 16);
        if (n == 0) {
            float z = g_xz[(size_t)row * (2 * DI) + DI + d];
            float sz = z / (1.f + __expf(-z));
            g_y[row * DI + d] = (p + Dd * u) * sz;
        }
    }
}

__global__ void k_zero(float* __restrict__ p, int nelem) {
    int i = blockIdx.x * blockDim.x + threadIdx.x;
    if (i < nelem) p[i] = 0.f;
}

__global__ void k_bias_relu(float* __restrict__ p, const float* __restrict__ b, int cols,
                            int nelem) {
    int i = blockIdx.x * blockDim.x + threadIdx.x;
    if (i < nelem) {
        float v = p[i] + b[i % cols];
        p[i] = fmaxf(v, 0.f);
    }
}

// ---------------- launch ----------------
extern "C" void kernel_launch(void* const* d_in, const int* in_sizes, int n_in,
                              void* d_out, int out_size) {
    const int* ids = (const int*)d_in[0];
    const float* embed = (const float*)d_in[1];
    const float* norm_f = (const float*)d_in[2];
    const float* norm_w = (const float*)d_in[3];
    const float* in_proj = (const float*)d_in[4];
    const float* conv_w = (const float*)d_in[5];
    const float* conv_b = (const float*)d_in[6];
    const float* x_proj = (const float*)d_in[7];
    const float* dt_w = (const float*)d_in[8];
    const float* dt_b = (const float*)d_in[9];
    const float* A_log = (const float*)d_in[10];
    const float* Dp = (const float*)d_in[11];
    const float* out_proj = (const float*)d_in[12];
    const float* ro_w1 = (const float*)d_in[13];
    const float* ro_b1 = (const float*)d_in[14];
    const float* ro_w2 = (const float*)d_in[15];
    const float* ro_b2 = (const float*)d_in[16];
    const float* ro_w3 = (const float*)d_in[17];
    const float* ro_b3 = (const float*)d_in[18];
    (void)in_sizes; (void)n_in; (void)out_size;

    float* out = (float*)d_out;
    float* out_main = out;                            // (B,L,V)
    float* out_ro = out + (size_t)BL * V;             // (B,L,V)
    float* out_hid = out + (size_t)2 * BL * V;        // (NL,B,L,DI,DS)

    float *x, *xn, *xz, *y, *h1, *h2;
    cudaGetSymbolAddress((void**)&x, g_x);
    cudaGetSymbolAddress((void**)&xn, g_xn);
    cudaGetSymbolAddress((void**)&xz, g_xz);
    cudaGetSymbolAddress((void**)&y, g_y);
    cudaGetSymbolAddress((void**)&h1, g_h1);
    cudaGetSymbolAddress((void**)&h2, g_h2);

    // raise dynamic smem limits once per instantiation
    auto kA = k_mma<false, false, 2, false, false>;  // NN atomic (in_proj, out_proj)
    auto kB = k_mma<true,  false, 0, true,  false>;  // lm head
    auto kC = k_mma<false, true,  2, false, false>;  // ro1 split-K
    auto kD = k_mma<false, false, 0, true,  true>;   // ro3 + bias
    cudaFuncSetAttribute(kA, cudaFuncAttributeMaxDynamicSharedMemorySize, SM_MMA);
    cudaFuncSetAttribute(kB, cudaFuncAttributeMaxDynamicSharedMemorySize, SM_MMA);
    cudaFuncSetAttribute(kC, cudaFuncAttributeMaxDynamicSharedMemorySize, SM_MMA);
    cudaFuncSetAttribute(kD, cudaFuncAttributeMaxDynamicSharedMemorySize, SM_MMA);

    k_embed<<<(BL * DM + 255) / 256, 256>>>(ids, embed);

    for (int l = 0; l < NLY; l++) {
        k_rmsnorm<<<BL, 256>>>(x, norm_w + (size_t)l * DM, xn);

        // xz = xn @ in_proj[l]  split-K z=2 -> 192 CTAs
        k_zero<<<(BL * 2 * DI + 255) / 256, 256>>>(xz, BL * 2 * DI);
        kA<<<dim3(2 * DI / 64, BL / 128, 2), 256, SM_MMA>>>(
            xn, in_proj + (size_t)l * DM * 2 * DI, xz, nullptr, 2 * DI, DM, 2 * DI, 2 * DI,
            DM / 2);

        // fused conv+silu, x_proj, dt+softplus
        k_cxd<<<BL, 256>>>(conv_w + (size_t)l * DI * DC, conv_b + (size_t)l * DI,
                           x_proj + (size_t)l * DI * 80, dt_w + (size_t)l * DTR * DI,
                           dt_b + (size_t)l * DI);

        // scan + fused gate
        k_scan<<<(BB * DI * DS) / 256, 256>>>(A_log + (size_t)l * DIDS, out_hid,
                                              Dp + (size_t)l * DI, l);

        // x += y @ out_proj[l]  split-K z=6 -> 144 CTAs, atomic into residual x
        kA<<<dim3(DM / 64, BL / 128, 6), 256, SM_MMA>>>(
            y, out_proj + (size_t)l * DI * DM, x, nullptr, DM, DI, DM, DM, DI / 6);
    }

    // final norm + tied lm head: main_logits = xn @ embed^T
    k_rmsnorm<<<BL, 256>>>(x, norm_f, xn);
    kB<<<dim3((V + 63) / 64, BL / 128, 1), 256, SM_MMA>>>(
        xn, embed, out_main, nullptr, V, DM, DM, V, DM);

    // readout layer 1: h1 = relu(feat @ ro_w1 + b1), split-K 16x6144
    k_zero<<<(BL * ROH + 255) / 256, 256>>>(h1, BL * ROH);
    kC<<<dim3(ROH / 64, BL / 128, 16), 256, SM_MMA>>>(
        out_hid, ro_w1, h1, nullptr, ROH, 0, ROH, ROH, (NLY * DIDS) / 16);
    k_bias_relu<<<(BL * ROH + 255) / 256, 256>>>(h1, ro_b1, ROH, BL * ROH);

    // readout layer 2: h2 = relu(h1 @ ro_w2 + b2)  (scalar, tiny)
    k_gemm<1><<<dim3(256 / 64, BL / 64), 256>>>(h1, ro_w2, h2, ro_b2, 256, ROH, 256, 256, ROH);

    // readout logits = h2 @ ro_w3 + b3
    kD<<<dim3((V + 63) / 64, BL / 128, 1), 256, SM_MMA>>>(
        h2, ro_w3, out_ro, ro_b3, V, 256, V, V, 256);
}